// round 2
// baseline (speedup 1.0000x reference)
#include <cuda_runtime.h>
#include <cstdint>

#define T_STEPS   4096
#define HID       2048
#define IN_DIM    128
#define NCTA      128
#define ROWS_CTA  16
#define NTHREADS  1024
#define LEAK      0.9f

// Persistent cross-replay state. Flags are MONOTONIC step counters (never reset),
// so graph replays are safe: each launch reads its own flag as `base`.
__device__ int   g_flags[NCTA][32];     // padded: one 128B sector per CTA
__device__ float g_actbuf[2][HID];      // double-buffered activation broadcast

// portable warp all-reduce (redux.f32 needs the sm_100a suffix target; ptxas
// stages PTX as sm_100 and rejects it, so use shfl butterfly instead)
__device__ __forceinline__ float warp_sum(float v) {
    v += __shfl_xor_sync(0xFFFFFFFFu, v, 16);
    v += __shfl_xor_sync(0xFFFFFFFFu, v, 8);
    v += __shfl_xor_sync(0xFFFFFFFFu, v, 4);
    v += __shfl_xor_sync(0xFFFFFFFFu, v, 2);
    v += __shfl_xor_sync(0xFFFFFFFFu, v, 1);
    return v;
}
__device__ __forceinline__ int ld_acquire(const int* p) {
    int v;
    asm volatile("ld.acquire.gpu.global.b32 %0, [%1];" : "=r"(v) : "l"(p));
    return v;
}
__device__ __forceinline__ void st_release(int* p, int v) {
    asm volatile("st.release.gpu.global.b32 [%0], %1;" :: "l"(p), "r"(v));
}

__global__ void __launch_bounds__(NTHREADS, 1)
reservoir_kernel(const float* __restrict__ input,   // [T, IN_DIM]
                 const float* __restrict__ w_ih,    // [HID, IN_DIM]
                 const float* __restrict__ b_ih,    // [HID]
                 const float* __restrict__ w_hh,    // [HID, HID]
                 float* __restrict__ out)           // [2, T, HID] (act, hid)
{
    __shared__ float w_ih_s[ROWS_CTA][IN_DIM];
    __shared__ float ip_s[ROWS_CTA];
    __shared__ float hid_s[ROWS_CTA];
    __shared__ float b_s[ROWS_CTA];
    __shared__ float red_s[32][8];

    const int tid  = threadIdx.x;
    const int cta  = blockIdx.x;
    const int r0   = cta * ROWS_CTA;
    const int half = tid >> 9;       // 0: rows r0..r0+7, 1: rows r0+8..r0+15
    const int slot = tid & 511;      // column group: cols [4*slot, 4*slot+4)
    const int warp = tid >> 5;
    const int lane = tid & 31;

    // ---- one-time setup ----
    for (int i = tid; i < ROWS_CTA * IN_DIM; i += NTHREADS)
        ((float*)w_ih_s)[i] = w_ih[r0 * IN_DIM + i];
    if (tid < ROWS_CTA) { b_s[tid] = b_ih[r0 + tid]; hid_s[tid] = 0.0f; }

    // w_hh rows for this CTA -> registers (128 KB/CTA, 32 regs/thread)
    float4 w4[8];
    {
        const float4* w_hh4 = (const float4*)w_hh;
        const int rbase = r0 + half * 8;
        #pragma unroll
        for (int i = 0; i < 8; i++)
            w4[i] = w_hh4[(size_t)(rbase + i) * (HID / 4) + slot];
    }

    const int base = g_flags[cta][0];   // previous launch left all flags equal
    __syncthreads();

    float* __restrict__ out_act = out;
    float* __restrict__ out_hid = out + (size_t)T_STEPS * HID;

    for (int t = 0; t < T_STEPS; t++) {
        // ---- Phase A: overlapped work before the block barrier ----
        if (warp >= 4 && warp < 8) {
            // warps 4..7 compute input projection ip[row] for this step
            const int wi = warp - 4;
            float4 u4 = ((const float4*)input)[t * (IN_DIM / 4) + lane];
            #pragma unroll
            for (int rr = 0; rr < 4; rr++) {
                const int row = wi * 4 + rr;
                float4 wv = ((const float4*)w_ih_s[row])[lane];
                float s = u4.x * wv.x + u4.y * wv.y + u4.z * wv.z + u4.w * wv.w;
                s = warp_sum(s);
                if (lane == 0) ip_s[row] = s + b_s[row];
            }
        } else if (tid < NCTA && t > 0) {
            // warps 0..3: wait until every CTA has published act_{t-1}
            const int target = base + t;
            while (ld_acquire(&g_flags[tid][0]) < target) {}
        }
        __syncthreads();

        // ---- Phase B: main recurrent matvec (register weights) ----
        float4 a4;
        if (t > 0) {
            // MUST bypass L1: cross-SM producer data, L1 is incoherent
            a4 = __ldcg(((const float4*)g_actbuf[(base + t - 1) & 1]) + slot);
        } else {
            a4 = make_float4(0.f, 0.f, 0.f, 0.f);   // act_{-1} = 0
        }
        float acc[8];
        #pragma unroll
        for (int i = 0; i < 8; i++)
            acc[i] = fmaf(w4[i].x, a4.x,
                     fmaf(w4[i].y, a4.y,
                     fmaf(w4[i].z, a4.z, w4[i].w * a4.w)));
        #pragma unroll
        for (int i = 0; i < 8; i++) {
            float s = warp_sum(acc[i]);
            if (lane == i) red_s[warp][i] = s;   // warps 0..15: rows 0..7; 16..31: rows 8..15
        }
        __syncthreads();

        // ---- Phase C: final reduce + nonlinearity + publish (threads 0..15) ----
        if (tid < ROWS_CTA) {
            const int row = tid;
            const int wb  = (row < 8) ? 0 : 16;
            const int j   = row & 7;
            float s = 0.0f;
            #pragma unroll
            for (int w = 0; w < 16; w++) s += red_s[wb + w][j];

            const float hprev = hid_s[row];
            const float nh = (1.0f - LEAK) * hprev + LEAK * (ip_s[row] + s);
            const float na = tanhf(nh);
            hid_s[row] = nh;

            const int gr = r0 + row;
            out_act[(size_t)t * HID + gr] = na;
            out_hid[(size_t)t * HID + gr] = nh;
            g_actbuf[(base + t) & 1][gr] = na;

            __syncwarp(0x0000FFFFu);
            if (tid == 0) st_release(&g_flags[cta][0], base + t + 1);
        }
        // protect ip_s/red_s from next-iteration overwrite before consumption
        __syncthreads();
    }
}

extern "C" void kernel_launch(void* const* d_in, const int* in_sizes, int n_in,
                              void* d_out, int out_size) {
    const float* input = (const float*)d_in[0];   // [4096, 128]
    const float* w_ih  = (const float*)d_in[1];   // [2048, 128]
    const float* b_ih  = (const float*)d_in[2];   // [2048]
    const float* w_hh  = (const float*)d_in[3];   // [2048, 2048]
    float* out = (float*)d_out;                   // [2, 4096, 2048]

    reservoir_kernel<<<NCTA, NTHREADS>>>(input, w_ih, b_ih, w_hh, out);
}